// round 1
// baseline (speedup 1.0000x reference)
#include <cuda_runtime.h>

typedef unsigned long long ull;

#define Bb   2
#define Nn   512
#define Hh   1024
#define HDd  512
#define Mm   (Bb * Nn)       // 1024 rows of flattened emb
#define NOUT (3 * HDd)       // 1536 fused GEMM output columns

// Scratch (static device globals — no allocation in kernel_launch)
__device__ float g_p[Mm * HDd];      // relu(emb@W_s1 + b_s1) * w_s2   [m][d]
__device__ float g_a2T[HDd * Mm];    // (emb@W1_start + b_e1)^T        [d][m]
__device__ float g_cT[HDd * Mm];     // (emb@W1_end)^T                 [d][m]

#define FMA2(acc, a, b) asm("fma.rn.f32x2 %0, %1, %2, %0;" : "+l"(acc) : "l"(a), "l"(b))
#define UNPK(lo, hi, v) asm("mov.b64 {%0, %1}, %2;" : "=f"(lo), "=f"(hi) : "l"(v))

// ---------------------------------------------------------------------------
// Fused GEMM: C[1024,1536] = emb[1024,1024] @ [W_s1 | W_e1[:H] | W_e1[H:]]
// BM=32, BN=64, BK=16, 256 threads, micro-tile 2x4 via packed f32x2.
// Epilogues differ per 512-column block (blk uniform per CTA):
//   blk0: g_p   = relu(x + b_s1)*w_s2        (row-major)
//   blk1: g_a2T = (x + b_e1)^T               (transposed for end kernel)
//   blk2: g_cT  = x^T
// ---------------------------------------------------------------------------
__global__ __launch_bounds__(256) void gemm_kernel(
    const float* __restrict__ emb,  const float* __restrict__ W_s1,
    const float* __restrict__ b_s1, const float* __restrict__ w_s2,
    const float* __restrict__ W_e1, const float* __restrict__ b_e1)
{
    __shared__ __align__(16) float2 As[16][32];  // [k][m], value duplicated in pair
    __shared__ __align__(16) float  Bs[16][64];  // [k][n]

    const int m0    = blockIdx.y * 32;
    const int n0    = blockIdx.x * 64;
    const int blk   = n0 >> 9;          // 0,1,2
    const int bcol0 = n0 & 511;
    const float* Bsrc = (blk == 0) ? W_s1 : (W_e1 + (blk == 2 ? Hh * HDd : 0));

    const int t  = threadIdx.x;
    const int tx = t & 15;              // 4 output cols at tx*4 (2 pairs)
    const int ty = t >> 4;              // 2 output rows at ty*2

    const int ar = t >> 2, aq = t & 3;    // A loader (t < 128)
    const int bkr = t >> 4, bnq = t & 15; // B loader (all threads)

    ull acc00 = 0, acc01 = 0, acc10 = 0, acc11 = 0;

    for (int kt = 0; kt < Hh; kt += 16) {
        if (t < 128) {
            float4 v = *(const float4*)(emb + (size_t)(m0 + ar) * Hh + kt + aq * 4);
            As[aq * 4 + 0][ar] = make_float2(v.x, v.x);
            As[aq * 4 + 1][ar] = make_float2(v.y, v.y);
            As[aq * 4 + 2][ar] = make_float2(v.z, v.z);
            As[aq * 4 + 3][ar] = make_float2(v.w, v.w);
        }
        {
            float4 v = *(const float4*)(Bsrc + (size_t)(kt + bkr) * HDd + bcol0 + bnq * 4);
            *(float4*)&Bs[bkr][bnq * 4] = v;
        }
        __syncthreads();
#pragma unroll
        for (int kk = 0; kk < 16; kk++) {
            ull a0 = ((const ull*)As[kk])[ty * 2 + 0];
            ull a1 = ((const ull*)As[kk])[ty * 2 + 1];
            ulonglong2 bb = *(const ulonglong2*)&Bs[kk][tx * 4];
            FMA2(acc00, a0, bb.x); FMA2(acc01, a0, bb.y);
            FMA2(acc10, a1, bb.x); FMA2(acc11, a1, bb.y);
        }
        __syncthreads();
    }

    float c00, c01, c02, c03, c10, c11, c12, c13;
    UNPK(c00, c01, acc00); UNPK(c02, c03, acc01);
    UNPK(c10, c11, acc10); UNPK(c12, c13, acc11);

    const int d0  = bcol0 + tx * 4;     // column within the 512-wide block
    const int m_0 = m0 + ty * 2;

    if (blk == 0) {
        const float4 bs = *(const float4*)(b_s1 + d0);
        const float4 ws = *(const float4*)(w_s2 + d0);
        float4 o0, o1;
        o0.x = fmaxf(c00 + bs.x, 0.f) * ws.x;
        o0.y = fmaxf(c01 + bs.y, 0.f) * ws.y;
        o0.z = fmaxf(c02 + bs.z, 0.f) * ws.z;
        o0.w = fmaxf(c03 + bs.w, 0.f) * ws.w;
        o1.x = fmaxf(c10 + bs.x, 0.f) * ws.x;
        o1.y = fmaxf(c11 + bs.y, 0.f) * ws.y;
        o1.z = fmaxf(c12 + bs.z, 0.f) * ws.z;
        o1.w = fmaxf(c13 + bs.w, 0.f) * ws.w;
        *(float4*)(g_p + (size_t)m_0 * HDd + d0)       = o0;
        *(float4*)(g_p + (size_t)(m_0 + 1) * HDd + d0) = o1;
    } else if (blk == 1) {
        const float4 be = *(const float4*)(b_e1 + d0);
        *(float2*)(g_a2T + (size_t)(d0 + 0) * Mm + m_0) = make_float2(c00 + be.x, c10 + be.x);
        *(float2*)(g_a2T + (size_t)(d0 + 1) * Mm + m_0) = make_float2(c01 + be.y, c11 + be.y);
        *(float2*)(g_a2T + (size_t)(d0 + 2) * Mm + m_0) = make_float2(c02 + be.z, c12 + be.z);
        *(float2*)(g_a2T + (size_t)(d0 + 3) * Mm + m_0) = make_float2(c03 + be.w, c13 + be.w);
    } else {
        *(float2*)(g_cT + (size_t)(d0 + 0) * Mm + m_0) = make_float2(c00, c10);
        *(float2*)(g_cT + (size_t)(d0 + 1) * Mm + m_0) = make_float2(c01, c11);
        *(float2*)(g_cT + (size_t)(d0 + 2) * Mm + m_0) = make_float2(c02, c12);
        *(float2*)(g_cT + (size_t)(d0 + 3) * Mm + m_0) = make_float2(c03, c13);
    }
}

// ---------------------------------------------------------------------------
// start_logits[m] = sum_d g_p[m][d] + b_s2   (one warp per row)
// ---------------------------------------------------------------------------
__global__ __launch_bounds__(256) void start_kernel(
    const float* __restrict__ b_s2, float* __restrict__ out)
{
    const int warp = (blockIdx.x * 256 + threadIdx.x) >> 5;  // 0..1023
    const int lane = threadIdx.x & 31;
    const float* row = g_p + (size_t)warp * HDd;

    float s = 0.f;
#pragma unroll
    for (int k = 0; k < 4; k++) {
        float4 v = *(const float4*)(row + (lane + 32 * k) * 4);
        s += v.x + v.y + v.z + v.w;
    }
#pragma unroll
    for (int off = 16; off; off >>= 1) s += __shfl_down_sync(0xffffffffu, s, off);
    if (lane == 0) out[warp] = s + b_s2[0];
}

// ---------------------------------------------------------------------------
// end_logits[b,i,j] = sum_d relu(a2[b,i,d] + c[b,j,d]) * w_e2[d] + b_e2
// Tile 32x32 (i x j) per CTA, d chunked by 64 through smem. 128 threads,
// micro-tile 2i x 4j. a2T / cT are pre-transposed so loads are coalesced and
// smem reads conflict-free (a: 8B broadcast pairs, c: contiguous 16B/thread).
// ---------------------------------------------------------------------------
__global__ __launch_bounds__(128) void end_kernel(
    const float* __restrict__ w_e2, const float* __restrict__ b_e2,
    float* __restrict__ out_end)
{
    __shared__ __align__(16) float Asm[64][32];  // [d][i]
    __shared__ __align__(16) float Csm[64][32];  // [d][j]
    __shared__ float Wsm[HDd];

    const int t  = threadIdx.x;
    const int bz = blockIdx.z;
    const int i0 = blockIdx.y * 32;
    const int j0 = blockIdx.x * 32;
    const int mi = bz * Nn + i0;   // column base in a2T
    const int mj = bz * Nn + j0;   // column base in cT

    for (int d = t; d < HDd; d += 128) Wsm[d] = w_e2[d];

    const int tx = t & 7;          // j micro: tx*4 .. +3
    const int ty = t >> 3;         // i micro: ty*2 .. +1
    const int ldr = t >> 3;        // loader d-row base (0..15)
    const int ldq = t & 7;         // loader float4 index (0..7 over 32 cols)

    float a00 = 0.f, a01 = 0.f, a02 = 0.f, a03 = 0.f;
    float a10 = 0.f, a11 = 0.f, a12 = 0.f, a13 = 0.f;

    for (int dc0 = 0; dc0 < HDd; dc0 += 64) {
        __syncthreads();
#pragma unroll
        for (int rep = 0; rep < 4; rep++) {
            int drow = rep * 16 + ldr;
            float4 va = *(const float4*)(g_a2T + (size_t)(dc0 + drow) * Mm + mi + ldq * 4);
            float4 vc = *(const float4*)(g_cT  + (size_t)(dc0 + drow) * Mm + mj + ldq * 4);
            *(float4*)&Asm[drow][ldq * 4] = va;
            *(float4*)&Csm[drow][ldq * 4] = vc;
        }
        __syncthreads();
#pragma unroll 8
        for (int dc = 0; dc < 64; dc++) {
            float w   = Wsm[dc0 + dc];
            float2 av = *(const float2*)&Asm[dc][ty * 2];
            float4 cv = *(const float4*)&Csm[dc][tx * 4];
            a00 = fmaf(fmaxf(av.x + cv.x, 0.f), w, a00);
            a01 = fmaf(fmaxf(av.x + cv.y, 0.f), w, a01);
            a02 = fmaf(fmaxf(av.x + cv.z, 0.f), w, a02);
            a03 = fmaf(fmaxf(av.x + cv.w, 0.f), w, a03);
            a10 = fmaf(fmaxf(av.y + cv.x, 0.f), w, a10);
            a11 = fmaf(fmaxf(av.y + cv.y, 0.f), w, a11);
            a12 = fmaf(fmaxf(av.y + cv.z, 0.f), w, a12);
            a13 = fmaf(fmaxf(av.y + cv.w, 0.f), w, a13);
        }
    }

    const float be = b_e2[0];
    float4 o0 = make_float4(a00 + be, a01 + be, a02 + be, a03 + be);
    float4 o1 = make_float4(a10 + be, a11 + be, a12 + be, a13 + be);
    size_t base = (size_t)bz * Nn * Nn + (size_t)(i0 + ty * 2) * Nn + j0 + tx * 4;
    *(float4*)(out_end + base)      = o0;
    *(float4*)(out_end + base + Nn) = o1;
}

// ---------------------------------------------------------------------------
extern "C" void kernel_launch(void* const* d_in, const int* in_sizes, int n_in,
                              void* d_out, int out_size)
{
    (void)in_sizes; (void)n_in; (void)out_size;
    const float* emb  = (const float*)d_in[0];
    const float* W_s1 = (const float*)d_in[1];
    const float* b_s1 = (const float*)d_in[2];
    const float* w_s2 = (const float*)d_in[3];
    const float* b_s2 = (const float*)d_in[4];
    const float* W_e1 = (const float*)d_in[5];
    const float* b_e1 = (const float*)d_in[6];
    const float* w_e2 = (const float*)d_in[7];
    const float* b_e2 = (const float*)d_in[8];
    float* out = (float*)d_out;

    dim3 gg(NOUT / 64, Mm / 32);          // 24 x 32 = 768 CTAs
    gemm_kernel<<<gg, 256>>>(emb, W_s1, b_s1, w_s2, W_e1, b_e1);

    start_kernel<<<Mm / 8, 256>>>(b_s2, out);

    dim3 ge(Nn / 32, Nn / 32, Bb);        // 16 x 16 x 2 = 512 CTAs
    end_kernel<<<ge, 128>>>(w_e2, b_e2, out + Mm);
}